// round 6
// baseline (speedup 1.0000x reference)
#include <cuda_runtime.h>
#include <cuda_fp16.h>

#define NPTS  100000
#define CIN   96
#define CHID  576
#define COUT  96

// ---------------- device scratch ----------------
__device__ __align__(16) signed char g_w1t8[(size_t)CHID * CIN];   // w1^T s8 [n][k]
__device__ __align__(16) __half      g_w3t [(size_t)COUT * CHID];  // w3^T f16 [n][k] (exact)
__device__ __align__(16) __half      g_w2h [9 * CHID];             // w2 f16 (exact)
__device__ __align__(16) __half      g_x1s [(size_t)NPTS * CHID];  // x1*256 (ints 0..1536)

__device__ __forceinline__ float clamp128f(float x) { return fminf(fmaxf(x, -128.0f), 128.0f); }
__device__ __forceinline__ float relu6f(float x)    { return fminf(fmaxf(x, 0.0f), 6.0f); }
__device__ __forceinline__ unsigned ld32(const void* p) { return *reinterpret_cast<const unsigned*>(p); }

__device__ __forceinline__ void mma16816(float* c, const unsigned* a, const unsigned* b) {
    asm volatile(
        "mma.sync.aligned.m16n8k16.row.col.f32.f16.f16.f32 "
        "{%0,%1,%2,%3}, {%4,%5,%6,%7}, {%8,%9}, {%0,%1,%2,%3};\n"
        : "+f"(c[0]), "+f"(c[1]), "+f"(c[2]), "+f"(c[3])
        : "r"(a[0]), "r"(a[1]), "r"(a[2]), "r"(a[3]), "r"(b[0]), "r"(b[1]));
}
__device__ __forceinline__ void imma16832(int* c, const unsigned* a, const unsigned* b) {
    asm volatile(
        "mma.sync.aligned.m16n8k32.row.col.s32.s8.s8.s32 "
        "{%0,%1,%2,%3}, {%4,%5,%6,%7}, {%8,%9}, {%0,%1,%2,%3};\n"
        : "+r"(c[0]), "+r"(c[1]), "+r"(c[2]), "+r"(c[3])
        : "r"(a[0]), "r"(a[1]), "r"(a[2]), "r"(a[3]), "r"(b[0]), "r"(b[1]));
}
__device__ __forceinline__ void cp16(void* s, const void* g) {
    unsigned sa = (unsigned)__cvta_generic_to_shared(s);
    asm volatile("cp.async.ca.shared.global [%0], [%1], 16;\n" :: "r"(sa), "l"(g));
}

// ---------------------------------------------------------------------------
// Kernel 0: weight conversions only (w1^T s8, w3^T f16, w2 f16).
// ---------------------------------------------------------------------------
__global__ __launch_bounds__(256) void kw_convert(
    const float* __restrict__ w1, const float* __restrict__ w3,
    const float* __restrict__ w2)
{
    const int i = blockIdx.x * 256 + threadIdx.x;
    if (i < CIN * CHID) {   // 55296
        const int n = i / CIN, k = i % CIN;
        g_w1t8[i] = (signed char)__float2int_rn(w1[(size_t)k * CHID + n]);
        const int n3 = i / CHID, k3 = i % CHID;
        g_w3t[i] = __float2half_rn(w3[(size_t)k3 * COUT + n3]);
    }
    if (i < 9 * CHID)
        g_w2h[i] = __float2half_rn(w2[i]);
}

// ---------------------------------------------------------------------------
// Kernel 1: x1s = 256 * relu6(clamp(requant(feats @ w1 + b1, s1)))  -- s8 IMMA
// One block per 128 sites; A staged ONCE (fp32->s8 in-kernel), loop over all
// 9 hid-tiles of 64 with cp.async double-buffered B. 8 warps (4m x 2n).
// ---------------------------------------------------------------------------
#define SA1 112
__global__ __launch_bounds__(256) void k1_expand(
    const float* __restrict__ feats,
    const float* __restrict__ b1, const float* __restrict__ s1)
{
    __shared__ __align__(16) signed char As[128 * SA1];
    __shared__ __align__(16) signed char Bs[2][64 * SA1];

    const int n0 = blockIdx.x * 128;
    const int tid = threadIdx.x;

    // stage + convert A: 128 rows x 96 floats -> s8
#pragma unroll
    for (int p = 0; p < 12; p++) {
        const int idx = tid + p * 256;          // 0..3071
        const int r = idx / 24, c4 = idx % 24;
        const int n = n0 + r;
        float4 f = make_float4(0.f, 0.f, 0.f, 0.f);
        if (n < NPTS)
            f = reinterpret_cast<const float4*>(feats + (size_t)n * CIN)[c4];
        const unsigned u = ((unsigned)(__float2int_rn(f.x) & 255))
                         | ((unsigned)(__float2int_rn(f.y) & 255) << 8)
                         | ((unsigned)(__float2int_rn(f.z) & 255) << 16)
                         | ((unsigned)(__float2int_rn(f.w) & 255) << 24);
        *reinterpret_cast<unsigned*>(As + r * SA1 + c4 * 4) = u;
    }
    // stage B(0)
#pragma unroll
    for (int p = 0; p < 2; p++) {
        const int idx = tid + p * 256;
        if (idx < 384) {
            const int r = idx / 6, s = idx % 6;
            cp16(Bs[0] + r * SA1 + s * 16, g_w1t8 + (size_t)r * CIN + s * 16);
        }
    }
    asm volatile("cp.async.commit_group;\n");
    __syncthreads();

    const int lane = tid & 31, wid = tid >> 5;
    const int wm = wid & 3, wn = wid >> 2;
    const int gid = lane >> 2, tig = lane & 3;

    for (int h = 0; h < 9; h++) {
        asm volatile("cp.async.wait_group 0;\n");
        __syncthreads();
        if (h + 1 < 9) {
            const int h0n = (h + 1) * 64;
#pragma unroll
            for (int p = 0; p < 2; p++) {
                const int idx = tid + p * 256;
                if (idx < 384) {
                    const int r = idx / 6, s = idx % 6;
                    cp16(Bs[(h + 1) & 1] + r * SA1 + s * 16,
                         g_w1t8 + (size_t)(h0n + r) * CIN + s * 16);
                }
            }
            asm volatile("cp.async.commit_group;\n");
        }
        const signed char* Bc = Bs[h & 1];

        int acc[2][4][4];
#pragma unroll
        for (int mi = 0; mi < 2; mi++)
#pragma unroll
            for (int ni = 0; ni < 4; ni++)
#pragma unroll
                for (int q = 0; q < 4; q++) acc[mi][ni][q] = 0;

#pragma unroll
        for (int ks = 0; ks < 3; ks++) {
            const int k0 = ks * 32;
            unsigned a[2][4], b[4][2];
#pragma unroll
            for (int mi = 0; mi < 2; mi++) {
                const signed char* pa = As + (wm * 32 + mi * 16 + gid) * SA1 + k0 + tig * 4;
                a[mi][0] = ld32(pa);
                a[mi][1] = ld32(pa + 8 * SA1);
                a[mi][2] = ld32(pa + 16);
                a[mi][3] = ld32(pa + 8 * SA1 + 16);
            }
#pragma unroll
            for (int ni = 0; ni < 4; ni++) {
                const signed char* pb = Bc + (wn * 32 + ni * 8 + gid) * SA1 + k0 + tig * 4;
                b[ni][0] = ld32(pb);
                b[ni][1] = ld32(pb + 16);
            }
#pragma unroll
            for (int mi = 0; mi < 2; mi++)
#pragma unroll
                for (int ni = 0; ni < 4; ni++)
                    imma16832(acc[mi][ni], a[mi], b[ni]);
        }

        const int hbase = h * 64;
#pragma unroll
        for (int ni = 0; ni < 4; ni++) {
            const int c = hbase + wn * 32 + ni * 8 + 2 * tig;
            const float bb0 = __ldg(b1 + c),     bb1 = __ldg(b1 + c + 1);
            const float m0  = rintf(__ldg(s1 + c)) * 256.0f;
            const float m1  = rintf(__ldg(s1 + c + 1)) * 256.0f;
#pragma unroll
            for (int mi = 0; mi < 2; mi++) {
                const int r = n0 + wm * 32 + mi * 16 + gid;
#pragma unroll
                for (int hh = 0; hh < 2; hh++) {
                    const int rr = r + hh * 8;
                    if (rr < NPTS) {
                        const float t0 = ((float)acc[mi][ni][2 * hh]     + bb0) * m0;
                        const float t1 = ((float)acc[mi][ni][2 * hh + 1] + bb1) * m1;
                        const float v0 = relu6f(clamp128f(t0 * (1.0f / 65536.0f)));
                        const float v1 = relu6f(clamp128f(t1 * (1.0f / 65536.0f)));
                        *reinterpret_cast<__half2*>(g_x1s + (size_t)rr * CHID + c) =
                            __halves2half2(__float2half_rn(v0 * 256.0f),
                                           __float2half_rn(v1 * 256.0f));
                    }
                }
            }
        }
    }
}

// ---------------------------------------------------------------------------
// Kernel 23 (fused dw + project) with windowed-gather x1 cache:
//   per block 64 sites; per 64-ch chunk (9 iters): cp.async-stream 3 windows
//   of 96 contiguous x1 rows (covering the 3 dy-runs of neighbor ids) into
//   smem, dw-requant into smem A (hi/lo fp16), HMMA vs double-buffered w3.
// ---------------------------------------------------------------------------
#define NIT3 9
#define SH3  72
#define XW   96           // window rows per dy-group
#define XS   72           // X row stride in halves

// dynamic smem layout (bytes), all 16B aligned:
#define OFF_BS   0                      // 2 * 96*72*2 = 27648
#define OFF_AH   27648                  // 64*72*2     =  9216
#define OFF_AL   36864                  //             =  9216
#define OFF_X    46080                  // 288*72*2    = 41472
#define OFF_W2   87552                  // 9*576*2     = 10368
#define OFF_B2   97920                  // 576*4       =  2304
#define OFF_S2   100224                 // 576*4       =  2304
#define OFF_NB   102528                 // 576*4       =  2304
#define OFF_BASE 104832                 // 4*4
#define SMEM_K23 104848

__global__ __launch_bounds__(256) void k23_fused(
    const int*   __restrict__ nbr,
    const float* __restrict__ b2,    const float* __restrict__ s2,
    const float* __restrict__ feats, const float* __restrict__ b3,
    const float* __restrict__ s3,    const float* __restrict__ s_main,
    const float* __restrict__ s_res, float* __restrict__ out)
{
    extern __shared__ __align__(16) char smem[];
    __half* BS  = reinterpret_cast<__half*>(smem + OFF_BS);   // [2][96*SH3]
    __half* AH  = reinterpret_cast<__half*>(smem + OFF_AH);   // [64*SH3]
    __half* AL  = reinterpret_cast<__half*>(smem + OFF_AL);
    __half* X   = reinterpret_cast<__half*>(smem + OFF_X);    // [3*XW][XS]
    __half* w2h = reinterpret_cast<__half*>(smem + OFF_W2);   // [9*576]
    float*  b2s = reinterpret_cast<float*>(smem + OFF_B2);
    float*  s2s = reinterpret_cast<float*>(smem + OFF_S2);
    int*    nbs = reinterpret_cast<int*>(smem + OFF_NB);      // [9][64]
    int*    base_s = reinterpret_cast<int*>(smem + OFF_BASE); // [3]

    const int n0  = blockIdx.x * 64;
    const int tid = threadIdx.x;
    const int lane = tid & 31, wid = tid >> 5;
    const int wm = wid & 1, wn = wid >> 1;
    const int gid = lane >> 2, tig = lane & 3;

    // ---- stage small constants via cp.async (group A) ----
    for (int idx = tid; idx < 648 + 144 + 144; idx += 256) {
        if (idx < 648)            cp16(w2h + idx * 8, g_w2h + idx * 8);
        else if (idx < 648 + 144) cp16(b2s + (idx - 648) * 4, b2 + (idx - 648) * 4);
        else                      cp16(s2s + (idx - 792) * 4, s2 + (idx - 792) * 4);
    }
    asm volatile("cp.async.commit_group;\n");

    // ---- stage neighbor ids (direct) ----
    for (int idx = tid; idx < 576; idx += 256) {
        const int kk = idx >> 6, jj = idx & 63;
        const int n = n0 + jj;
        nbs[idx] = (n < NPTS) ? __ldg(nbr + (size_t)kk * NPTS + n) : -1;
    }
    __syncthreads();

    // ---- per-dy-group window base = clamp(min valid id) ----
    if (tid < 96) {
        const int g = tid >> 5, ln = tid & 31;
        int m = 0x7FFFFFFF;
        for (int e = ln; e < 192; e += 32) {
            const int v = nbs[g * 192 + e];
            if (v >= 0) m = min(m, v);
        }
#pragma unroll
        for (int d = 16; d > 0; d >>= 1)
            m = min(m, __shfl_xor_sync(0xFFFFFFFFu, m, d));
        if (ln == 0) {
            if (m == 0x7FFFFFFF) m = 0;
            base_s[g] = min(max(m, 0), NPTS - XW);
        }
    }
    __syncthreads();

    int bReg[3] = {base_s[0], base_s[1], base_s[2]};

    // ---- stage X(0) + BS(0) ----
    auto stageX = [&](int it) {
        const int kc0 = it * 64;
#pragma unroll
        for (int p = 0; p < 9; p++) {
            const int idx = tid + p * 256;      // 0..2303
            const int g = idx / 768;
            const int rl = (idx - g * 768) >> 3;
            const int seg = idx & 7;
            const int row = base_s[g] + rl;
            cp16(X + (g * XW + rl) * XS + seg * 8,
                 g_x1s + (size_t)row * CHID + kc0 + seg * 8);
        }
    };
    auto stageB = [&](int it) {
        const int k0 = it * 64;
        __half* dst = BS + (it & 1) * (96 * SH3);
#pragma unroll
        for (int p = 0; p < 3; p++) {
            const int idx = tid + p * 256;
            const int r = idx >> 3, s = idx & 7;
            cp16(dst + r * SH3 + s * 8, g_w3t + (size_t)r * CHID + k0 + s * 8);
        }
    };
    stageX(0);
    stageB(0);
    asm volatile("cp.async.commit_group;\n");

    float acc[2][3][4];
#pragma unroll
    for (int mi = 0; mi < 2; mi++)
#pragma unroll
        for (int ni = 0; ni < 3; ni++)
#pragma unroll
            for (int q = 0; q < 4; q++) acc[mi][ni][q] = 0.0f;

    const int site = tid >> 2;
    const int cloc = (tid & 3) * 16;

    for (int it = 0; it < NIT3; it++) {
        asm volatile("cp.async.wait_group 0;\n");
        __syncthreads();     // X(it)/BS(it) ready; A consumed by MMA(it-1)

        // ---- depthwise for this 64-ch chunk ----
        const int kc = it * 64 + cloc;
        float accv[16];
#pragma unroll
        for (int q = 0; q < 16; q++) accv[q] = 0.0f;

#pragma unroll
        for (int tap = 0; tap < 9; tap++) {
            const int nb = nbs[tap * 64 + site];
            if (nb >= 0) {
                const int g = tap / 3;
                const unsigned off = (unsigned)(nb - bReg[g]);
                uint4 u0, u1;
                if (off < XW) {
                    const __half* sx = X + (g * XW + (int)off) * XS + cloc;
                    u0 = *reinterpret_cast<const uint4*>(sx);
                    u1 = *reinterpret_cast<const uint4*>(sx + 8);
                } else {
                    const __half* gx = g_x1s + (size_t)nb * CHID + kc;
                    u0 = *reinterpret_cast<const uint4*>(gx);
                    u1 = *reinterpret_cast<const uint4*>(gx + 8);
                }
                const __half* wp = w2h + tap * CHID + kc;
                const uint4 w0 = *reinterpret_cast<const uint4*>(wp);
                const uint4 w1v = *reinterpret_cast<const uint4*>(wp + 8);
                const unsigned xu[8] = {u0.x, u0.y, u0.z, u0.w, u1.x, u1.y, u1.z, u1.w};
                const unsigned wu[8] = {w0.x, w0.y, w0.z, w0.w, w1v.x, w1v.y, w1v.z, w1v.w};
#pragma unroll
                for (int q = 0; q < 8; q++) {
                    const float2 xf = __half22float2(*reinterpret_cast<const __half2*>(&xu[q]));
                    const float2 wf = __half22float2(*reinterpret_cast<const __half2*>(&wu[q]));
                    accv[2 * q]     = fmaf(xf.x, wf.x, accv[2 * q]);
                    accv[2 * q + 1] = fmaf(xf.y, wf.y, accv[2 * q + 1]);
                }
            }
        }
        // requant -> hi/lo fp16 -> A tiles
        unsigned hh[8], llv[8];
#pragma unroll
        for (int q = 0; q < 8; q++) {
#pragma unroll
            for (int e = 0; e < 2; e++) {
                const int j = 2 * q + e;
                const float d = accv[j] * (1.0f / 256.0f) + b2s[kc + j];
                const float m = rintf(s2s[kc + j]) * 256.0f;
                const float v = relu6f(clamp128f(d * m * (1.0f / 65536.0f)));
                const __half h = __float2half_rn(v);
                const __half l = __float2half_rn(v - __half2float(h));
                if (e == 0) { hh[q] = (unsigned)__half_as_ushort(h); llv[q] = (unsigned)__half_as_ushort(l); }
                else        { hh[q] |= (unsigned)__half_as_ushort(h) << 16; llv[q] |= (unsigned)__half_as_ushort(l) << 16; }
            }
        }
        {
            __half* dh = AH + site * SH3 + cloc;
            __half* dl = AL + site * SH3 + cloc;
            *reinterpret_cast<uint4*>(dh)     = make_uint4(hh[0], hh[1], hh[2], hh[3]);
            *reinterpret_cast<uint4*>(dh + 8) = make_uint4(hh[4], hh[5], hh[6], hh[7]);
            *reinterpret_cast<uint4*>(dl)     = make_uint4(llv[0], llv[1], llv[2], llv[3]);
            *reinterpret_cast<uint4*>(dl + 8) = make_uint4(llv[4], llv[5], llv[6], llv[7]);
        }
        __syncthreads();     // A visible; X fully consumed

        if (it + 1 < NIT3) {
            stageX(it + 1);      // overlaps with MMA below
            stageB(it + 1);
            asm volatile("cp.async.commit_group;\n");
        }

        // ---- MMA: 4 k-steps of 16, hi+lo planes ----
        const __half* BSc = BS + (it & 1) * (96 * SH3);
#pragma unroll
        for (int ks = 0; ks < 4; ks++) {
            const int kk = ks * 16;
            unsigned ah[2][4], al[2][4], bb[3][2];
#pragma unroll
            for (int mi = 0; mi < 2; mi++) {
                const int row = wm * 32 + mi * 16 + gid;
                const __half* ph = AH + row * SH3 + kk + 2 * tig;
                ah[mi][0] = ld32(ph);
                ah[mi][1] = ld32(ph + 8 * SH3);
                ah[mi][2] = ld32(ph + 8);
                ah[mi][3] = ld32(ph + 8 * SH3 + 8);
                const __half* pl = AL + row * SH3 + kk + 2 * tig;
                al[mi][0] = ld32(pl);
                al[mi][1] = ld32(pl + 8 * SH3);
                al[mi][2] = ld32(pl + 8);
                al[mi][3] = ld32(pl + 8 * SH3 + 8);
            }
#pragma unroll
            for (int ni = 0; ni < 3; ni++) {
                const __half* pb = BSc + (wn * 24 + ni * 8 + gid) * SH3 + kk + 2 * tig;
                bb[ni][0] = ld32(pb);
                bb[ni][1] = ld32(pb + 8);
            }
#pragma unroll
            for (int mi = 0; mi < 2; mi++)
#pragma unroll
                for (int ni = 0; ni < 3; ni++) {
                    mma16816(acc[mi][ni], ah[mi], bb[ni]);
                    mma16816(acc[mi][ni], al[mi], bb[ni]);
                }
        }
    }

    const float rm = rintf(__ldg(s_main)) * 256.0f;
    const float rr = rintf(__ldg(s_res)) * 256.0f;

#pragma unroll
    for (int ni = 0; ni < 3; ni++) {
        const int c = wn * 24 + ni * 8 + 2 * tig;
        const float bb0 = __ldg(b3 + c),     bb1 = __ldg(b3 + c + 1);
        const float m0  = rintf(__ldg(s3 + c)) * 256.0f;
        const float m1  = rintf(__ldg(s3 + c + 1)) * 256.0f;
#pragma unroll
        for (int mi = 0; mi < 2; mi++) {
            const int r = n0 + wm * 32 + mi * 16 + gid;
#pragma unroll
            for (int h = 0; h < 2; h++) {
                const int rr_ = r + h * 8;
                if (rr_ < NPTS) {
                    const float v0 = clamp128f((acc[mi][ni][2 * h]     + bb0) * m0 * (1.0f / 65536.0f));
                    const float v1 = clamp128f((acc[mi][ni][2 * h + 1] + bb1) * m1 * (1.0f / 65536.0f));
                    const float2 f = *reinterpret_cast<const float2*>(
                        feats + (size_t)rr_ * CIN + c);
                    float2 o;
                    o.x = rm * v0 + rr * f.x;
                    o.y = rm * v1 + rr * f.y;
                    *reinterpret_cast<float2*>(out + (size_t)rr_ * COUT + c) = o;
                }
            }
        }
    }
}

// ---------------------------------------------------------------------------
extern "C" void kernel_launch(void* const* d_in, const int* in_sizes, int n_in,
                              void* d_out, int out_size)
{
    const float* feats = (const float*)d_in[0];
    const int*   nbr   = (const int*)  d_in[1];
    const float* w1    = (const float*)d_in[2];
    const float* b1    = (const float*)d_in[3];
    const float* w2    = (const float*)d_in[4];
    const float* b2    = (const float*)d_in[5];
    const float* w3    = (const float*)d_in[6];
    const float* b3    = (const float*)d_in[7];
    const float* s1    = (const float*)d_in[8];
    const float* s2    = (const float*)d_in[9];
    const float* s3    = (const float*)d_in[10];
    const float* smain = (const float*)d_in[11];
    const float* sres  = (const float*)d_in[12];
    float* out = (float*)d_out;

    static int smem_set = 0;
    if (!smem_set) {
        cudaFuncSetAttribute(k23_fused, cudaFuncAttributeMaxDynamicSharedMemorySize, SMEM_K23);
        smem_set = 1;
    }

    kw_convert<<<(CIN * CHID + 255) / 256, 256>>>(w1, w3, w2);
    k1_expand <<<(NPTS + 127) / 128, 256>>>(feats, b1, s1);
    k23_fused <<<(NPTS + 63) / 64, 256, SMEM_K23>>>(nbr, b2, s2,
                                                    feats, b3, s3, smain, sres, out);
}

// round 7
// speedup vs baseline: 1.3849x; 1.3849x over previous
#include <cuda_runtime.h>
#include <cuda_fp16.h>

#define NPTS  100000
#define CIN   96
#define CHID  576
#define COUT  96

// ---------------- device scratch ----------------
__device__ __align__(16) signed char g_w1t8[(size_t)CHID * CIN];   // w1^T s8 [n][k]
__device__ __align__(16) __half      g_w3t [(size_t)COUT * CHID];  // w3^T f16 [n][k] (exact)
__device__ __align__(16) __half      g_x1s [(size_t)NPTS * CHID];  // x1*256 (ints 0..1536)

__device__ __forceinline__ float clamp128f(float x) { return fminf(fmaxf(x, -128.0f), 128.0f); }
__device__ __forceinline__ float relu6f(float x)    { return fminf(fmaxf(x, 0.0f), 6.0f); }
__device__ __forceinline__ unsigned ld32(const void* p) { return *reinterpret_cast<const unsigned*>(p); }

__device__ __forceinline__ void mma16816(float* c, const unsigned* a, const unsigned* b) {
    asm volatile(
        "mma.sync.aligned.m16n8k16.row.col.f32.f16.f16.f32 "
        "{%0,%1,%2,%3}, {%4,%5,%6,%7}, {%8,%9}, {%0,%1,%2,%3};\n"
        : "+f"(c[0]), "+f"(c[1]), "+f"(c[2]), "+f"(c[3])
        : "r"(a[0]), "r"(a[1]), "r"(a[2]), "r"(a[3]), "r"(b[0]), "r"(b[1]));
}
__device__ __forceinline__ void imma16832(int* c, const unsigned* a, const unsigned* b) {
    asm volatile(
        "mma.sync.aligned.m16n8k32.row.col.s32.s8.s8.s32 "
        "{%0,%1,%2,%3}, {%4,%5,%6,%7}, {%8,%9}, {%0,%1,%2,%3};\n"
        : "+r"(c[0]), "+r"(c[1]), "+r"(c[2]), "+r"(c[3])
        : "r"(a[0]), "r"(a[1]), "r"(a[2]), "r"(a[3]), "r"(b[0]), "r"(b[1]));
}
__device__ __forceinline__ void cp16(void* s, const void* g) {
    unsigned sa = (unsigned)__cvta_generic_to_shared(s);
    asm volatile("cp.async.ca.shared.global [%0], [%1], 16;\n" :: "r"(sa), "l"(g));
}

// ---------------------------------------------------------------------------
// Kernel 0: weight conversions only (w1^T s8, w3^T f16).
// ---------------------------------------------------------------------------
__global__ __launch_bounds__(256) void kw_convert(
    const float* __restrict__ w1, const float* __restrict__ w3)
{
    const int i = blockIdx.x * 256 + threadIdx.x;
    if (i < CIN * CHID) {   // 55296
        const int n = i / CIN, k = i % CIN;
        g_w1t8[i] = (signed char)__float2int_rn(w1[(size_t)k * CHID + n]);
        const int n3 = i / CHID, k3 = i % CHID;
        g_w3t[i] = __float2half_rn(w3[(size_t)k3 * COUT + n3]);
    }
}

// ---------------------------------------------------------------------------
// Kernel 1: x1s = 256 * relu6(clamp(requant(feats @ w1 + b1, s1)))  -- s8 IMMA
// One block per 128 sites; A staged ONCE (fp32->s8 in-kernel), loop over all
// 9 hid-tiles of 64 with cp.async double-buffered B. 8 warps (4m x 2n).
// ---------------------------------------------------------------------------
#define SA1 112
__global__ __launch_bounds__(256) void k1_expand(
    const float* __restrict__ feats,
    const float* __restrict__ b1, const float* __restrict__ s1)
{
    __shared__ __align__(16) signed char As[128 * SA1];
    __shared__ __align__(16) signed char Bs[2][64 * SA1];

    const int n0 = blockIdx.x * 128;
    const int tid = threadIdx.x;

    // stage + convert A: 128 rows x 96 floats -> s8
#pragma unroll
    for (int p = 0; p < 12; p++) {
        const int idx = tid + p * 256;          // 0..3071
        const int r = idx / 24, c4 = idx % 24;
        const int n = n0 + r;
        float4 f = make_float4(0.f, 0.f, 0.f, 0.f);
        if (n < NPTS)
            f = reinterpret_cast<const float4*>(feats + (size_t)n * CIN)[c4];
        const unsigned u = ((unsigned)(__float2int_rn(f.x) & 255))
                         | ((unsigned)(__float2int_rn(f.y) & 255) << 8)
                         | ((unsigned)(__float2int_rn(f.z) & 255) << 16)
                         | ((unsigned)(__float2int_rn(f.w) & 255) << 24);
        *reinterpret_cast<unsigned*>(As + r * SA1 + c4 * 4) = u;
    }
    // stage B(0)
#pragma unroll
    for (int p = 0; p < 2; p++) {
        const int idx = tid + p * 256;
        if (idx < 384) {
            const int r = idx / 6, s = idx % 6;
            cp16(Bs[0] + r * SA1 + s * 16, g_w1t8 + (size_t)r * CIN + s * 16);
        }
    }
    asm volatile("cp.async.commit_group;\n");
    __syncthreads();

    const int lane = tid & 31, wid = tid >> 5;
    const int wm = wid & 3, wn = wid >> 2;
    const int gid = lane >> 2, tig = lane & 3;

    for (int h = 0; h < 9; h++) {
        asm volatile("cp.async.wait_group 0;\n");
        __syncthreads();
        if (h + 1 < 9) {
            const int h0n = (h + 1) * 64;
#pragma unroll
            for (int p = 0; p < 2; p++) {
                const int idx = tid + p * 256;
                if (idx < 384) {
                    const int r = idx / 6, s = idx % 6;
                    cp16(Bs[(h + 1) & 1] + r * SA1 + s * 16,
                         g_w1t8 + (size_t)(h0n + r) * CIN + s * 16);
                }
            }
            asm volatile("cp.async.commit_group;\n");
        }
        const signed char* Bc = Bs[h & 1];

        int acc[2][4][4];
#pragma unroll
        for (int mi = 0; mi < 2; mi++)
#pragma unroll
            for (int ni = 0; ni < 4; ni++)
#pragma unroll
                for (int q = 0; q < 4; q++) acc[mi][ni][q] = 0;

#pragma unroll
        for (int ks = 0; ks < 3; ks++) {
            const int k0 = ks * 32;
            unsigned a[2][4], b[4][2];
#pragma unroll
            for (int mi = 0; mi < 2; mi++) {
                const signed char* pa = As + (wm * 32 + mi * 16 + gid) * SA1 + k0 + tig * 4;
                a[mi][0] = ld32(pa);
                a[mi][1] = ld32(pa + 8 * SA1);
                a[mi][2] = ld32(pa + 16);
                a[mi][3] = ld32(pa + 8 * SA1 + 16);
            }
#pragma unroll
            for (int ni = 0; ni < 4; ni++) {
                const signed char* pb = Bc + (wn * 32 + ni * 8 + gid) * SA1 + k0 + tig * 4;
                b[ni][0] = ld32(pb);
                b[ni][1] = ld32(pb + 16);
            }
#pragma unroll
            for (int mi = 0; mi < 2; mi++)
#pragma unroll
                for (int ni = 0; ni < 4; ni++)
                    imma16832(acc[mi][ni], a[mi], b[ni]);
        }

        const int hbase = h * 64;
#pragma unroll
        for (int ni = 0; ni < 4; ni++) {
            const int c = hbase + wn * 32 + ni * 8 + 2 * tig;
            const float bb0 = __ldg(b1 + c),     bb1 = __ldg(b1 + c + 1);
            const float m0  = rintf(__ldg(s1 + c)) * 256.0f;
            const float m1  = rintf(__ldg(s1 + c + 1)) * 256.0f;
#pragma unroll
            for (int mi = 0; mi < 2; mi++) {
                const int r = n0 + wm * 32 + mi * 16 + gid;
#pragma unroll
                for (int hh = 0; hh < 2; hh++) {
                    const int rr = r + hh * 8;
                    if (rr < NPTS) {
                        const float t0 = ((float)acc[mi][ni][2 * hh]     + bb0) * m0;
                        const float t1 = ((float)acc[mi][ni][2 * hh + 1] + bb1) * m1;
                        const float v0 = relu6f(clamp128f(t0 * (1.0f / 65536.0f)));
                        const float v1 = relu6f(clamp128f(t1 * (1.0f / 65536.0f)));
                        *reinterpret_cast<__half2*>(g_x1s + (size_t)rr * CHID + c) =
                            __halves2half2(__float2half_rn(v0 * 256.0f),
                                           __float2half_rn(v1 * 256.0f));
                    }
                }
            }
        }
    }
}

// ---------------------------------------------------------------------------
// Kernel 23 (fused dw + project), R4-proven version (direct L2 gather):
//   per block: 64 sites x 96 out cols.
//   per iter (9 x 64 channels): depthwise-gather+requant -> smem A (hi/lo fp16),
//   HMMA against cp.async double-buffered w3 tile; epilogue w/ residual.
// ---------------------------------------------------------------------------
#define NIT3 9
#define SH3  72   // A/B row stride in halves (64+8): 36 words == 4 mod 32, conflict-free

// dynamic smem layout (bytes):
#define OFF_BS   0                          // 2 * 96*72*2 = 27648
#define OFF_AH   27648                      // 64*72*2     =  9216
#define OFF_AL   36864                      //             =  9216
#define OFF_W2   46080                      // 9*576*4     = 20736
#define OFF_B2   66816                      // 576*4
#define OFF_M2   69120                      // 576*4
#define OFF_NB   71424                      // 9*64*4
#define SMEM_K23 73728

__global__ __launch_bounds__(256) void k23_fused(
    const int*   __restrict__ nbr,   const float* __restrict__ w2,
    const float* __restrict__ b2,    const float* __restrict__ s2,
    const float* __restrict__ feats, const float* __restrict__ b3,
    const float* __restrict__ s3,    const float* __restrict__ s_main,
    const float* __restrict__ s_res, float* __restrict__ out)
{
    extern __shared__ __align__(16) char smem[];
    __half* BS  = reinterpret_cast<__half*>(smem + OFF_BS);   // [2][96*SH3]
    __half* AH  = reinterpret_cast<__half*>(smem + OFF_AH);   // [64*SH3]
    __half* AL  = reinterpret_cast<__half*>(smem + OFF_AL);
    float*  w2f = reinterpret_cast<float*>(smem + OFF_W2);    // [9][576]
    float*  b2s = reinterpret_cast<float*>(smem + OFF_B2);
    float*  m2s = reinterpret_cast<float*>(smem + OFF_M2);
    int*    nbs = reinterpret_cast<int*>(smem + OFF_NB);      // [9][64]

    const int n0  = blockIdx.x * 64;
    const int tid = threadIdx.x;
    const int lane = tid & 31, wid = tid >> 5;
    const int wm = wid & 1, wn = wid >> 1;
    const int gid = lane >> 2, tig = lane & 3;

    // ---- one-time staging ----
    for (int idx = tid; idx < 9 * CHID; idx += 256) w2f[idx] = __ldg(w2 + idx);
    for (int idx = tid; idx < CHID; idx += 256) {
        b2s[idx] = __ldg(b2 + idx);
        m2s[idx] = rintf(__ldg(s2 + idx)) * 256.0f;
    }
    for (int idx = tid; idx < 9 * 64; idx += 256) {
        const int kk = idx >> 6, jj = idx & 63;
        const int n = n0 + jj;
        nbs[idx] = (n < NPTS) ? __ldg(nbr + (size_t)kk * NPTS + n) : -1;
    }
    // stage B chunk 0
#pragma unroll
    for (int p = 0; p < 3; p++) {
        const int idx = tid + p * 256;
        const int r = idx >> 3, s = idx & 7;
        cp16(&BS[r * SH3 + s * 8], g_w3t + (size_t)r * CHID + 0 + s * 8);
    }
    asm volatile("cp.async.commit_group;\n");
    __syncthreads();

    float acc[2][3][4];
#pragma unroll
    for (int mi = 0; mi < 2; mi++)
#pragma unroll
        for (int ni = 0; ni < 3; ni++)
#pragma unroll
            for (int q = 0; q < 4; q++) acc[mi][ni][q] = 0.0f;

    const int site = tid >> 2;          // 0..63
    const int cloc = (tid & 3) * 16;    // channel offset within 64-chunk

    for (int it = 0; it < NIT3; it++) {
        const int bsel = it & 1;
        __half* BSc = BS + bsel * (96 * SH3);

        // stage next B chunk (overlaps with dw compute below)
        if (it + 1 < NIT3) {
            const int k0n = (it + 1) * 64;
            __half* BSn = BS + (bsel ^ 1) * (96 * SH3);
#pragma unroll
            for (int p = 0; p < 3; p++) {
                const int idx = tid + p * 256;
                const int r = idx >> 3, s = idx & 7;
                cp16(&BSn[r * SH3 + s * 8], g_w3t + (size_t)r * CHID + k0n + s * 8);
            }
            asm volatile("cp.async.commit_group;\n");
        }

        // ---- depthwise compute for this 64-channel chunk ----
        const int kc = it * 64 + cloc;      // global channel base (16 ch)
        float accv[16];
#pragma unroll
        for (int q = 0; q < 16; q++) accv[q] = 0.0f;

#pragma unroll
        for (int tap = 0; tap < 9; tap++) {
            const int nb = nbs[tap * 64 + site];
            if (nb >= 0) {
                const uint4* px = reinterpret_cast<const uint4*>(
                    g_x1s + (size_t)nb * CHID + kc);
                const uint4 u0 = px[0], u1 = px[1];
                unsigned uu[8] = {u0.x, u0.y, u0.z, u0.w, u1.x, u1.y, u1.z, u1.w};
                const float* wf = w2f + tap * CHID + kc;
#pragma unroll
                for (int q = 0; q < 8; q++) {
                    const float2 f = __half22float2(*reinterpret_cast<__half2*>(&uu[q]));
                    accv[2 * q]     = fmaf(f.x, wf[2 * q],     accv[2 * q]);
                    accv[2 * q + 1] = fmaf(f.y, wf[2 * q + 1], accv[2 * q + 1]);
                }
            }
        }
        // requant -> hi/lo fp16
        unsigned hh[8], llv[8];
#pragma unroll
        for (int q = 0; q < 8; q++) {
#pragma unroll
            for (int e = 0; e < 2; e++) {
                const int j = 2 * q + e;
                const float d = accv[j] * (1.0f / 256.0f) + b2s[kc + j];
                const float v = relu6f(clamp128f(d * m2s[kc + j] * (1.0f / 65536.0f)));
                const __half h = __float2half_rn(v);
                const __half l = __float2half_rn(v - __half2float(h));
                if (e == 0) { hh[q] = (unsigned)__half_as_ushort(h); llv[q] = (unsigned)__half_as_ushort(l); }
                else        { hh[q] |= (unsigned)__half_as_ushort(h) << 16; llv[q] |= (unsigned)__half_as_ushort(l) << 16; }
            }
        }
        {
            __half* dh = AH + site * SH3 + cloc;
            __half* dl = AL + site * SH3 + cloc;
            *reinterpret_cast<uint4*>(dh)     = make_uint4(hh[0], hh[1], hh[2], hh[3]);
            *reinterpret_cast<uint4*>(dh + 8) = make_uint4(hh[4], hh[5], hh[6], hh[7]);
            *reinterpret_cast<uint4*>(dl)     = make_uint4(llv[0], llv[1], llv[2], llv[3]);
            *reinterpret_cast<uint4*>(dl + 8) = make_uint4(llv[4], llv[5], llv[6], llv[7]);
        }

        if (it + 1 < NIT3) asm volatile("cp.async.wait_group 1;\n");
        else               asm volatile("cp.async.wait_group 0;\n");
        __syncthreads();   // A tile written + B(it) arrived

        // ---- MMA over this chunk: 4 k-steps of 16, hi+lo planes ----
#pragma unroll
        for (int ks = 0; ks < 4; ks++) {
            const int kk = ks * 16;
            unsigned ah[2][4], al[2][4], bb[3][2];
#pragma unroll
            for (int mi = 0; mi < 2; mi++) {
                const int row = wm * 32 + mi * 16 + gid;
                const __half* ph = AH + row * SH3 + kk + 2 * tig;
                ah[mi][0] = ld32(ph);
                ah[mi][1] = ld32(ph + 8 * SH3);
                ah[mi][2] = ld32(ph + 8);
                ah[mi][3] = ld32(ph + 8 * SH3 + 8);
                const __half* pl = AL + row * SH3 + kk + 2 * tig;
                al[mi][0] = ld32(pl);
                al[mi][1] = ld32(pl + 8 * SH3);
                al[mi][2] = ld32(pl + 8);
                al[mi][3] = ld32(pl + 8 * SH3 + 8);
            }
#pragma unroll
            for (int ni = 0; ni < 3; ni++) {
                const __half* pb = BSc + (wn * 24 + ni * 8 + gid) * SH3 + kk + 2 * tig;
                bb[ni][0] = ld32(pb);
                bb[ni][1] = ld32(pb + 8);
            }
#pragma unroll
            for (int mi = 0; mi < 2; mi++)
#pragma unroll
                for (int ni = 0; ni < 3; ni++) {
                    mma16816(acc[mi][ni], ah[mi], bb[ni]);
                    mma16816(acc[mi][ni], al[mi], bb[ni]);
                }
        }
        __syncthreads();   // MMA done before next iter overwrites A tiles
    }

    const float rm = rintf(__ldg(s_main)) * 256.0f;
    const float rr = rintf(__ldg(s_res)) * 256.0f;

#pragma unroll
    for (int ni = 0; ni < 3; ni++) {
        const int c = wn * 24 + ni * 8 + 2 * tig;
        const float bb0 = __ldg(b3 + c),     bb1 = __ldg(b3 + c + 1);
        const float m0  = rintf(__ldg(s3 + c)) * 256.0f;
        const float m1  = rintf(__ldg(s3 + c + 1)) * 256.0f;
#pragma unroll
        for (int mi = 0; mi < 2; mi++) {
            const int r = n0 + wm * 32 + mi * 16 + gid;
#pragma unroll
            for (int h = 0; h < 2; h++) {
                const int rr_ = r + h * 8;
                if (rr_ < NPTS) {
                    const float v0 = clamp128f((acc[mi][ni][2 * h]     + bb0) * m0 * (1.0f / 65536.0f));
                    const float v1 = clamp128f((acc[mi][ni][2 * h + 1] + bb1) * m1 * (1.0f / 65536.0f));
                    const float2 f = *reinterpret_cast<const float2*>(
                        feats + (size_t)rr_ * CIN + c);
                    float2 o;
                    o.x = rm * v0 + rr * f.x;
                    o.y = rm * v1 + rr * f.y;
                    *reinterpret_cast<float2*>(out + (size_t)rr_ * COUT + c) = o;
                }
            }
        }
    }
}

// ---------------------------------------------------------------------------
extern "C" void kernel_launch(void* const* d_in, const int* in_sizes, int n_in,
                              void* d_out, int out_size)
{
    const float* feats = (const float*)d_in[0];
    const int*   nbr   = (const int*)  d_in[1];
    const float* w1    = (const float*)d_in[2];
    const float* b1    = (const float*)d_in[3];
    const float* w2    = (const float*)d_in[4];
    const float* b2    = (const float*)d_in[5];
    const float* w3    = (const float*)d_in[6];
    const float* b3    = (const float*)d_in[7];
    const float* s1    = (const float*)d_in[8];
    const float* s2    = (const float*)d_in[9];
    const float* s3    = (const float*)d_in[10];
    const float* smain = (const float*)d_in[11];
    const float* sres  = (const float*)d_in[12];
    float* out = (float*)d_out;

    static int smem_set = 0;
    if (!smem_set) {
        cudaFuncSetAttribute(k23_fused, cudaFuncAttributeMaxDynamicSharedMemorySize, SMEM_K23);
        smem_set = 1;
    }

    kw_convert<<<(CIN * CHID + 255) / 256, 256>>>(w1, w3);
    k1_expand <<<(NPTS + 127) / 128, 256>>>(feats, b1, s1);
    k23_fused <<<(NPTS + 63) / 64, 256, SMEM_K23>>>(nbr, w2, b2, s2,
                                                    feats, b3, s3, smain, sres, out);
}